// round 3
// baseline (speedup 1.0000x reference)
#include <cuda_runtime.h>

// CapsuleLayer dynamic routing, fp32.
//   inputs: (64, 512, 128) fp32
//   W:      (512, 16, 128, 32) fp32
//   num_routing = 3 (fixed by setup_inputs)
//   out:    (64, 16, 32) fp32
//
// Plan:
//   K1 uhat_kernel : u_hat[b,i,j,d] = sum_k inputs[b,i,k] * W[i,j,k,d]
//                    one block per i; A held in SMEM duplicated as (a,a) pairs so the
//                    outer product maps onto packed fma.rn.f32x2 (FFMA2) with no MOVs.
//   K2 s_squash    : s[b,j,d] = sum_i c[b,i,j]*u_hat ; v = squash(s)
//   K3 agree       : b[b,i,j] (+)= dot_d(v[b,j,:], u_hat[b,i,j,:]) ; c = softmax_j(b)
//   Sequence: K1, K2(uniform), K3(first), K2, K3, K2(final -> d_out)

#define B_    64
#define ICAPS 512
#define IDIM  128
#define NCAPS 16
#define ODIM  32

// Scratch (allocation-free rule: __device__ globals)
__device__ float g_uhat[(size_t)B_ * ICAPS * NCAPS * ODIM];  // 67 MB
__device__ float g_b[(size_t)B_ * ICAPS * NCAPS];
__device__ float g_c[(size_t)B_ * ICAPS * NCAPS];
__device__ float g_v[(size_t)B_ * NCAPS * ODIM];

__device__ __forceinline__ void fma2(unsigned long long& c,
                                     unsigned long long a,
                                     unsigned long long b) {
    asm("fma.rn.f32x2 %0, %1, %2, %0;" : "+l"(c) : "l"(a), "l"(b));
}

// ---------------------------------------------------------------------------
// K1: u_hat GEMM. grid = 512 (one block per input capsule i), 256 threads.
// Dynamic SMEM 96KB: Adup[128][128] (A duplicated along b) + Ws[2][128][32].
// Thread tile: 4 b-rows x 4 d-cols; 128 threads per j, 2 j's concurrently.
// ---------------------------------------------------------------------------
__global__ void __launch_bounds__(256, 2)
uhat_kernel(const float* __restrict__ x, const float* __restrict__ W) {
    extern __shared__ float smem[];
    float* Adup = smem;                 // [k][2b], row stride 128 floats
    float* Wsh  = smem + 128 * 128;     // [jj][k][d], 2*128*32

    const int i   = blockIdx.x;
    const int tid = threadIdx.x;

    // Load A = inputs[:, i, :] duplicated: Adup[k][2b] = Adup[k][2b+1] = x[b,i,k]
    // Lanes vary b (conflict-free STS.64); global reads are strided but tiny (32KB/block).
    for (int idx = tid; idx < 64 * 32; idx += 256) {
        int b  = idx & 63;
        int kq = idx >> 6;  // float4 index along k
        float4 v = *reinterpret_cast<const float4*>(
            x + ((size_t)b * ICAPS + i) * IDIM + kq * 4);
        int k = kq * 4;
        *reinterpret_cast<float2*>(Adup + (k + 0) * 128 + 2 * b) = make_float2(v.x, v.x);
        *reinterpret_cast<float2*>(Adup + (k + 1) * 128 + 2 * b) = make_float2(v.y, v.y);
        *reinterpret_cast<float2*>(Adup + (k + 2) * 128 + 2 * b) = make_float2(v.z, v.z);
        *reinterpret_cast<float2*>(Adup + (k + 3) * 128 + 2 * b) = make_float2(v.w, v.w);
    }

    const int jj = tid >> 7;   // which of 2 concurrent j's
    const int t  = tid & 127;
    const int bt = t >> 3;     // 0..15 -> b0 = 4*bt
    const int dt = t & 7;      // 0..7  -> d0 = 4*dt

    const float* Wi = W + (size_t)i * NCAPS * IDIM * ODIM;

    for (int jp = 0; jp < 8; ++jp) {
        __syncthreads();  // previous Ws consumers done (also covers Adup stores at jp=0)
        // Load W tiles for j = 2*jp, 2*jp+1 (each tile is 4096 contiguous floats)
        {
            const float4* src = reinterpret_cast<const float4*>(
                Wi + (size_t)jp * 2 * IDIM * ODIM);
            float4* dst = reinterpret_cast<float4*>(Wsh);
            #pragma unroll
            for (int l = tid; l < 2048; l += 256) dst[l] = src[l];
        }
        __syncthreads();

        unsigned long long c2[4][2];
        #pragma unroll
        for (int q = 0; q < 4; ++q) { c2[q][0] = 0ull; c2[q][1] = 0ull; }

        const float* wbase = Wsh + jj * 128 * 32 + dt * 4;
        const float* abase = Adup + bt * 8;

        #pragma unroll 8
        for (int k = 0; k < 128; ++k) {
            ulonglong2 w   = *reinterpret_cast<const ulonglong2*>(wbase + k * 32);
            ulonglong2 a01 = *reinterpret_cast<const ulonglong2*>(abase + k * 128);
            ulonglong2 a23 = *reinterpret_cast<const ulonglong2*>(abase + k * 128 + 4);
            fma2(c2[0][0], a01.x, w.x); fma2(c2[0][1], a01.x, w.y);
            fma2(c2[1][0], a01.y, w.x); fma2(c2[1][1], a01.y, w.y);
            fma2(c2[2][0], a23.x, w.x); fma2(c2[2][1], a23.x, w.y);
            fma2(c2[3][0], a23.y, w.x); fma2(c2[3][1], a23.y, w.y);
        }

        const int j  = jp * 2 + jj;
        const int b0 = bt * 4;
        const int d0 = dt * 4;
        #pragma unroll
        for (int bb = 0; bb < 4; ++bb) {
            union { unsigned long long u; float2 f; } u0, u1;
            u0.u = c2[bb][0];
            u1.u = c2[bb][1];
            float4 o = make_float4(u0.f.x, u0.f.y, u1.f.x, u1.f.y);
            *reinterpret_cast<float4*>(
                g_uhat + ((((size_t)(b0 + bb) * ICAPS + i) * NCAPS + j) * ODIM + d0)) = o;
        }
    }
}

// ---------------------------------------------------------------------------
// K2: s = sum_i c * u_hat, then squash. grid = (64, 16), 256 threads.
// uniform=1 -> c = 1/16 (softmax of zeros). final=1 -> write d_out, else g_v.
// ---------------------------------------------------------------------------
__global__ void s_squash_kernel(float* __restrict__ out, int uniform, int final_iter) {
    const int b = blockIdx.x;
    const int j = blockIdx.y;
    const int d = threadIdx.x & 31;
    const int g = threadIdx.x >> 5;  // 8 i-groups

    const float* U = g_uhat + (((size_t)b * ICAPS) * NCAPS + j) * ODIM + d;
    const float* C = g_c + (size_t)b * ICAPS * NCAPS + j;

    float acc = 0.f;
    #pragma unroll 4
    for (int i = g; i < ICAPS; i += 8) {
        float u  = U[(size_t)i * NCAPS * ODIM];
        float cc = uniform ? 0.0625f : C[(size_t)i * NCAPS];
        acc = fmaf(cc, u, acc);
    }

    __shared__ float sm[8][32];
    sm[g][d] = acc;
    __syncthreads();

    if (threadIdx.x < 32) {
        float s = 0.f;
        #pragma unroll
        for (int g2 = 0; g2 < 8; ++g2) s += sm[g2][d];
        float ss = s * s;
        #pragma unroll
        for (int o = 16; o; o >>= 1) ss += __shfl_xor_sync(0xffffffffu, ss, o);
        // squash: scale = ss/(1+ss)/sqrt(ss+1e-7)
        float scale = ss / (1.f + ss) * rsqrtf(ss + 1e-7f);
        float* dst = final_iter ? out : g_v;
        dst[((size_t)b * NCAPS + j) * ODIM + d] = scale * s;
    }
}

// ---------------------------------------------------------------------------
// K3: agreement + softmax. One warp per (b,i). grid = 4096 x 256 (8 warps/blk).
// addPrev=0 treats previous b as 0 (first routing update).
// ---------------------------------------------------------------------------
__global__ void agree_kernel(int addPrev) {
    const int gw   = (blockIdx.x * blockDim.x + threadIdx.x) >> 5;  // b*512+i
    const int lane = threadIdx.x & 31;
    if (gw >= B_ * ICAPS) return;
    const int b = gw >> 9;

    const float* U = g_uhat + (size_t)gw * NCAPS * ODIM;
    const float* V = g_v + (size_t)b * NCAPS * ODIM;

    float bj[NCAPS];
    #pragma unroll
    for (int j = 0; j < NCAPS; ++j) {
        float p = U[j * ODIM + lane] * V[j * ODIM + lane];
        #pragma unroll
        for (int o = 16; o; o >>= 1) p += __shfl_xor_sync(0xffffffffu, p, o);
        bj[j] = p;  // broadcast to all lanes by xor-reduce
    }

    float* Bp = g_b + (size_t)gw * NCAPS;
    if (addPrev) {
        #pragma unroll
        for (int j = 0; j < NCAPS; ++j) bj[j] += Bp[j];
    }

    // softmax over j (replicated across lanes; 16 values)
    float m = bj[0];
    #pragma unroll
    for (int j = 1; j < NCAPS; ++j) m = fmaxf(m, bj[j]);
    float ej[NCAPS];
    float sum = 0.f;
    #pragma unroll
    for (int j = 0; j < NCAPS; ++j) { ej[j] = expf(bj[j] - m); sum += ej[j]; }
    float inv = 1.f / sum;

    float bsel = 0.f, csel = 0.f;
    #pragma unroll
    for (int j = 0; j < NCAPS; ++j)
        if (lane == j) { bsel = bj[j]; csel = ej[j] * inv; }
    if (lane < NCAPS) {
        Bp[lane] = bsel;
        g_c[(size_t)gw * NCAPS + lane] = csel;
    }
}

// ---------------------------------------------------------------------------
extern "C" void kernel_launch(void* const* d_in, const int* in_sizes, int n_in,
                              void* d_out, int out_size) {
    const float* x = (const float*)d_in[0];
    const float* W = (const float*)d_in[1];
    float* out = (float*)d_out;

    cudaFuncSetAttribute(uhat_kernel,
                         cudaFuncAttributeMaxDynamicSharedMemorySize, 96 * 1024);

    // u_hat
    uhat_kernel<<<ICAPS, 256, 96 * 1024>>>(x, W);

    dim3 gs(B_, NCAPS);
    // r = 0: c uniform
    s_squash_kernel<<<gs, 256>>>(out, /*uniform=*/1, /*final=*/0);
    agree_kernel<<<4096, 256>>>(/*addPrev=*/0);
    // r = 1
    s_squash_kernel<<<gs, 256>>>(out, 0, 0);
    agree_kernel<<<4096, 256>>>(/*addPrev=*/1);
    // r = 2 (final)
    s_squash_kernel<<<gs, 256>>>(out, 0, /*final=*/1);
}